// round 15
// baseline (speedup 1.0000x reference)
#include <cuda_runtime.h>
#include <cstdint>

namespace {

constexpr int BATCH     = 20000;
constexpr int MTOT      = 49;
constexpr int KDIM      = 128;
constexpr int NDIM      = 128;
constexpr int TILE_ROWS = 128;
constexpr int NTILES    = 4;                      // row-tiles per CTA
constexpr int NTHREADS  = 256;

constexpr int PLANE      = 16384;                 // 128 rows x 128B = 64 fp16 k
constexpr int W_OFF      = 4 * PLANE;             // A 4-deep ring first
constexpr int SMEM_TOTAL = W_OFF + 2 * PLANE;     // 64KB A + 32KB W = 98304 B

constexpr size_t ROW_STRIDE = (size_t)MTOT * KDIM;   // floats between batch rows

// SW128-style layout: smem row = 128B (64 fp16 k), 8 x 16B segs, seg' = seg^(row&7).
// Consumer: ldmatrix.m8n8.x4.b16 -> m16n8k16 fp16 mma (mapping validated R5-R8).
// R15: fp16 staging regs (16 not 32), batched 6-LDSM issue per k16 step,
// fully unrolled plane loop on the nt==NTILES fast path.

__device__ __forceinline__ uint32_t smem_u32(const void* p) {
    uint32_t a;
    asm("{ .reg .u64 t; cvta.to.shared.u64 t, %1; cvt.u32.u64 %0, t; }"
        : "=r"(a) : "l"(p));
    return a;
}

__device__ __forceinline__ uint32_t f16x2(float lo, float hi) {
    uint32_t r;                    // low half = lo (lower k index)
    asm("cvt.rn.f16x2.f32 %0, %2, %1;" : "=r"(r) : "f"(lo), "f"(hi));
    return r;
}

__device__ __forceinline__ void sts128(uint32_t addr, uint32_t a, uint32_t b,
                                       uint32_t c, uint32_t d) {
    asm volatile("st.shared.v4.b32 [%0], {%1, %2, %3, %4};"
                 :: "r"(addr), "r"(a), "r"(b), "r"(c), "r"(d) : "memory");
}

__device__ __forceinline__ void ldsm4(uint32_t& r0, uint32_t& r1,
                                      uint32_t& r2, uint32_t& r3, uint32_t addr) {
    asm volatile("ldmatrix.sync.aligned.m8n8.x4.shared.b16 {%0,%1,%2,%3}, [%4];"
                 : "=r"(r0), "=r"(r1), "=r"(r2), "=r"(r3) : "r"(addr));
}

__device__ __forceinline__ void mma_f16(float* c, uint32_t a0, uint32_t a1,
                                        uint32_t a2, uint32_t a3,
                                        uint32_t b0, uint32_t b1) {
    asm volatile(
        "mma.sync.aligned.m16n8k16.row.col.f32.f16.f16.f32 "
        "{%0,%1,%2,%3}, {%4,%5,%6,%7}, {%8,%9}, {%0,%1,%2,%3};"
        : "+f"(c[0]), "+f"(c[1]), "+f"(c[2]), "+f"(c[3])
        : "r"(a0), "r"(a1), "r"(a2), "r"(a3), "r"(b0), "r"(b1));
}

__global__ void __launch_bounds__(NTHREADS, 2)
so3_linear_kernel(const float* __restrict__ in,
                  const float* __restrict__ w,
                  const float* __restrict__ bias,
                  float* __restrict__ out)
{
    extern __shared__ char smem[];
    const uint32_t sb = smem_u32(smem);

    const int tid  = threadIdx.x;
    const int lane = tid & 31;
    const int wid  = tid >> 5;
    const int g    = lane >> 2;
    const int t    = lane & 3;

    const int m = blockIdx.y;
    int l = 0;
    while ((l + 1) * (l + 1) <= m) l++;
    const float* wl = w + (size_t)l * NDIM * KDIM;

    // ---- producer mapping: 8 threads/row, each 32B fp32 -> 16B fp16 seg ----
    const int prow = tid >> 3;               // 0..31 (+32*i covers 128 rows)
    const int seg  = tid & 7;
    const uint32_t stsOff0 = (uint32_t)(prow * 128 + ((seg ^ (prow & 7)) << 4));

    const int rowBase0 = blockIdx.x * (NTILES * TILE_ROWS);
    const int nt = min(NTILES, (BATCH - rowBase0 + TILE_ROWS - 1) / TILE_ROWS);

    const float* aCol = in + (size_t)m * KDIM + seg * 8;

    uint32_t st[16];                          // fp16x2 staging for one plane

    // ---- consumer mapping (validated R5-R8) ----
    const int warp_row = (wid & 3) * 32;
    const int warp_col = (wid >> 2) * 64;
    const int x7 = lane & 7;
    const int aRowOff = ((lane >> 3) & 1) * 8 + x7;
    const int aSh     = lane >> 4;
    const int bRowOff = ((lane >> 4) & 1) * 8 + x7;
    const int bSh     = (lane >> 3) & 1;
    const uint32_t aBaseOff = (uint32_t)((warp_row + aRowOff) * 128);
    const uint32_t bBaseOff = (uint32_t)((warp_col + bRowOff) * 128);
    uint32_t aSegT[4], bSegT[4];
    #pragma unroll
    for (int ks = 0; ks < 4; ks++) {
        aSegT[ks] = (uint32_t)(((2 * ks + aSh) ^ x7) << 4);
        bSegT[ks] = (uint32_t)(((2 * ks + bSh) ^ x7) << 4);
    }

    float acc[2][8][4] = {};
    const bool addb = (m == 0);

    auto ldgPlane = [&](int p, int nplanes) {
        if (p >= nplanes) return;
        const int tl = p >> 1, h = p & 1;
        #pragma unroll
        for (int i = 0; i < 4; i++) {
            int r = rowBase0 + tl * TILE_ROWS + prow + 32 * i;
            if (r >= BATCH) r = BATCH - 1;   // clamped rows never stored
            const float* q = aCol + (size_t)r * ROW_STRIDE + h * 64;
            float4 q0 = *reinterpret_cast<const float4*>(q);
            float4 q1 = *reinterpret_cast<const float4*>(q + 4);
            st[4 * i + 0] = f16x2(q0.x, q0.y);
            st[4 * i + 1] = f16x2(q0.z, q0.w);
            st[4 * i + 2] = f16x2(q1.x, q1.y);
            st[4 * i + 3] = f16x2(q1.z, q1.w);
        }
    };
    auto stsPlane = [&](int p, int nplanes) {
        if (p >= nplanes) return;
        const uint32_t ad = sb + (uint32_t)((p & 3) * PLANE) + stsOff0;
        #pragma unroll
        for (int i = 0; i < 4; i++)
            sts128(ad + i * 4096, st[4 * i], st[4 * i + 1],
                                  st[4 * i + 2], st[4 * i + 3]);
    };

    auto planeBody = [&](int gj, int nplanes) {
        const int h = gj & 1;

        // producer one plane ahead: STS(gj+2) (loaded at gj-1), LDG(gj+3)
        stsPlane(gj + 2, nplanes);
        ldgPlane(gj + 3, nplanes);

        const uint32_t Ab = sb + (uint32_t)((gj & 3) * PLANE) + aBaseOff;
        const uint32_t Wb = sb + (uint32_t)(W_OFF + h * PLANE) + bBaseOff;

        #pragma unroll
        for (int ks = 0; ks < 4; ks++) {               // 4 x k16 = k64
            uint32_t af[4], ag[4], b[16];
            ldsm4(af[0], af[1], af[2], af[3], Ab + aSegT[ks]);
            ldsm4(ag[0], ag[1], ag[2], ag[3], Ab + 2048 + aSegT[ks]);
            #pragma unroll
            for (int np = 0; np < 4; np++)
                ldsm4(b[4 * np], b[4 * np + 1], b[4 * np + 2], b[4 * np + 3],
                      Wb + (uint32_t)(np * 2048) + bSegT[ks]);
            #pragma unroll
            for (int np = 0; np < 4; np++) {
                mma_f16(acc[0][2 * np],     af[0], af[1], af[2], af[3],
                        b[4 * np], b[4 * np + 1]);
                mma_f16(acc[0][2 * np + 1], af[0], af[1], af[2], af[3],
                        b[4 * np + 2], b[4 * np + 3]);
                mma_f16(acc[1][2 * np],     ag[0], ag[1], ag[2], ag[3],
                        b[4 * np], b[4 * np + 1]);
                mma_f16(acc[1][2 * np + 1], ag[0], ag[1], ag[2], ag[3],
                        b[4 * np + 2], b[4 * np + 3]);
            }
        }

        if (h == 1) {
            // ---- epilogue for tile gj>>1, then the (only) barrier ----
            const int rb = rowBase0 + (gj >> 1) * TILE_ROWS;
            #pragma unroll
            for (int mi = 0; mi < 2; mi++) {
                #pragma unroll
                for (int ni = 0; ni < 8; ni++) {
                    const int cc = warp_col + ni * 8 + 2 * t;
                    const int r0 = rb + warp_row + mi * 16 + g;
                    float2 v0 = make_float2(acc[mi][ni][0], acc[mi][ni][1]);
                    float2 v1 = make_float2(acc[mi][ni][2], acc[mi][ni][3]);
                    if (addb) {
                        const float b0v = bias[cc], b1v = bias[cc + 1];
                        v0.x += b0v; v0.y += b1v;
                        v1.x += b0v; v1.y += b1v;
                    }
                    if (r0 < BATCH)
                        *reinterpret_cast<float2*>(out + (((size_t)r0 * MTOT + m) * NDIM + cc)) = v0;
                    if (r0 + 8 < BATCH)
                        *reinterpret_cast<float2*>(out + (((size_t)(r0 + 8) * MTOT + m) * NDIM + cc)) = v1;
                    acc[mi][ni][0] = 0.f; acc[mi][ni][1] = 0.f;
                    acc[mi][ni][2] = 0.f; acc[mi][ni][3] = 0.f;
                }
            }
            __syncthreads();                  // one barrier per 2 planes (k128)
        }
    };

    // ---- prologue: planes 0,1 staged; plane 2 in regs; W staged ----
    {
        const int npl = nt * 2;
        ldgPlane(0, npl); stsPlane(0, npl);
        ldgPlane(1, npl); stsPlane(1, npl);
        ldgPlane(2, npl);

        const float* wRow = wl + (size_t)prow * KDIM + seg * 8;
        #pragma unroll
        for (int p = 0; p < 2; p++) {
            const uint32_t wb = sb + (uint32_t)(W_OFF + p * PLANE) + stsOff0;
            #pragma unroll
            for (int i = 0; i < 4; i++) {
                const float* q = wRow + i * (32 * KDIM) + p * 64;
                float4 q0 = *reinterpret_cast<const float4*>(q);
                float4 q1 = *reinterpret_cast<const float4*>(q + 4);
                sts128(wb + i * 4096,
                       f16x2(q0.x, q0.y), f16x2(q0.z, q0.w),
                       f16x2(q1.x, q1.y), f16x2(q1.z, q1.w));
            }
        }
        __syncthreads();
    }

    if (nt == NTILES) {
        // fast path: all bounds compile-time, plane loop fully unrolled
        #pragma unroll
        for (int gj = 0; gj < 2 * NTILES; gj++)
            planeBody(gj, 2 * NTILES);
    } else {
        const int npl = nt * 2;
        for (int gj = 0; gj < npl; gj++)
            planeBody(gj, npl);
    }
}

}  // namespace

extern "C" void kernel_launch(void* const* d_in, const int* in_sizes, int n_in,
                              void* d_out, int out_size) {
    (void)in_sizes; (void)n_in; (void)out_size;
    const float* in   = (const float*)d_in[0];
    const float* w    = (const float*)d_in[1];
    const float* bias = (const float*)d_in[2];
    float* out        = (float*)d_out;

    cudaFuncSetAttribute(so3_linear_kernel,
                         cudaFuncAttributeMaxDynamicSharedMemorySize, SMEM_TOTAL);

    dim3 grid((BATCH + NTILES * TILE_ROWS - 1) / (NTILES * TILE_ROWS), MTOT);
    so3_linear_kernel<<<grid, NTHREADS, SMEM_TOTAL>>>(in, w, bias, out);
}